// round 2
// baseline (speedup 1.0000x reference)
#include <cuda_runtime.h>

#define NVOX  40000
#define TPTS  32
#define BEVH  496
#define BEVW  432
#define NCELL (BEVH*BEVW)      /* 214272 */
#define CAP   32
#define EPSF  1e-5f

// ---------------- scratch (static device memory; no allocations) ----------------
__device__ float g_voxelwise[NVOX * 64];
__device__ int   g_cellCount[NCELL];
__device__ int   g_cellMem[NCELL * CAP];
__device__ int   g_workCell[NVOX];
__device__ int   g_workNumv[NVOX];
__device__ int   g_workMem[NVOX * 16];
__device__ int   g_workCount;

// mish(y) = y * tanh(softplus(y)) = y * ((1+e^y)^2 - 1)/((1+e^y)^2 + 1)
__device__ __forceinline__ float mish(float y) {
    float u = __expf(fminf(y, 25.0f));
    float t = 1.0f + u;
    t = t * t;
    return y * __fdividef(t - 1.0f, t + 1.0f);
}

// ---------------- zero kernels ----------------
__global__ void k_zero_out(float4* out, int n4) {
    int i = blockIdx.x * blockDim.x + threadIdx.x;
    int stride = gridDim.x * blockDim.x;
    float4 z = make_float4(0.f, 0.f, 0.f, 0.f);
    for (; i < n4; i += stride) out[i] = z;
}

__global__ void k_zero_meta() {
    int i = blockIdx.x * blockDim.x + threadIdx.x;
    if (i < NCELL) g_cellCount[i] = 0;
    if (i == 0) g_workCount = 0;
}

// ---------------- VFE: one 64-thread block per voxel (persistent) ----------------
__global__ __launch_bounds__(64, 5) void k_vfe(
    const float* __restrict__ feat, const int* __restrict__ nvox,
    const float* __restrict__ W1, const float* __restrict__ bn1,
    const float* __restrict__ W2, const float* __restrict__ bn2,
    const float* __restrict__ W3, const float* __restrict__ bn3,
    const float* __restrict__ W4, const float* __restrict__ bn4)
{
    __shared__ float W1s[64];
    __shared__ float W2s[512];
    __shared__ float s1s[8], o1s[8], s2s[32], o2s[32];
    __shared__ float fs[256];         // features [32][8]
    __shared__ float p1s[32 * 9];     // pitch 9 (bank-friendly)
    __shared__ float agg1s[8];
    __shared__ float p2s[32 * 33];    // pitch 33
    __shared__ float agg2s[32];
    __shared__ float x2s[32 * 64];    // row-major, float4-broadcast reads
    __shared__ float x3s[2 * 64];

    const int tid = threadIdx.x;

    // ---- one-time block setup ----
    W1s[tid] = W1[tid];
    for (int i = tid; i < 512; i += 64) W2s[i] = W2[i];
    if (tid < 8) {
        float s = bn1[tid] * rsqrtf(bn1[24 + tid] + EPSF);
        s1s[tid] = s;
        o1s[tid] = bn1[8 + tid] - bn1[16 + tid] * s;
    }
    if (tid < 32) {
        float s = bn2[tid] * rsqrtf(bn2[96 + tid] + EPSF);
        s2s[tid] = s;
        o2s[tid] = bn2[32 + tid] - bn2[64 + tid] * s;
    }
    // per-thread: rows of W3 and W4 in registers (thread = output channel)
    float w3r[64], w4r[64];
#pragma unroll
    for (int k = 0; k < 16; k++) {
        float4 a = __ldg((const float4*)(W3 + tid * 64) + k);
        w3r[4*k] = a.x; w3r[4*k+1] = a.y; w3r[4*k+2] = a.z; w3r[4*k+3] = a.w;
        float4 b = __ldg((const float4*)(W4 + tid * 64) + k);
        w4r[4*k] = b.x; w4r[4*k+1] = b.y; w4r[4*k+2] = b.z; w4r[4*k+3] = b.w;
    }
    const float s3 = bn3[tid] * rsqrtf(bn3[192 + tid] + EPSF);
    const float o3 = bn3[64 + tid] - bn3[128 + tid] * s3;
    const float s4 = bn4[tid] * rsqrtf(bn4[192 + tid] + EPSF);
    const float o4 = bn4[64 + tid] - bn4[128 + tid] * s4;
    __syncthreads();

    const int t = tid & 31;
    const int half = tid >> 5;

    for (int v = blockIdx.x; v < NVOX; v += gridDim.x) {
        ((float4*)fs)[tid] = ((const float4*)(feat + (size_t)v * 256))[tid];
        const int numv = nvox[v];
        __syncthreads();

        // ---- stage 1: 8 -> 8, thread (t, half) computes 4 channels ----
        {
            float4 fa = ((const float4*)fs)[t * 2];
            float4 fb = ((const float4*)fs)[t * 2 + 1];
            float f[8] = {fa.x, fa.y, fa.z, fa.w, fb.x, fb.y, fb.z, fb.w};
#pragma unroll
            for (int j = 0; j < 4; j++) {
                int c = half * 4 + j;
                float acc = 0.f;
#pragma unroll
                for (int i = 0; i < 8; i++) acc = fmaf(f[i], W1s[c * 8 + i], acc);
                p1s[t * 9 + c] = mish(fmaf(acc, s1s[c], o1s[c]));
            }
        }
        __syncthreads();
        if (tid < 8) {
            float mx = -3.0e38f;
#pragma unroll
            for (int tt = 0; tt < 32; tt++) mx = fmaxf(mx, p1s[tt * 9 + tid]);
            agg1s[tid] = mx;
        }
        __syncthreads();

        // ---- stage 2: 16 -> 32, thread (t, half) computes 16 channels ----
        {
            float x1[16];
#pragma unroll
            for (int i = 0; i < 8; i++) { x1[i] = p1s[t * 9 + i]; x1[8 + i] = agg1s[i]; }
#pragma unroll
            for (int j = 0; j < 16; j++) {
                int c = half * 16 + j;
                float acc = 0.f;
#pragma unroll
                for (int i = 0; i < 16; i++) acc = fmaf(x1[i], W2s[c * 16 + i], acc);
                p2s[t * 33 + c] = mish(fmaf(acc, s2s[c], o2s[c]));
            }
        }
        __syncthreads();
        if (tid < 32) {
            float mx = -3.0e38f;
#pragma unroll
            for (int tt = 0; tt < 32; tt++) mx = fmaxf(mx, p2s[tt * 33 + tid]);
            agg2s[tid] = mx;
        }
        __syncthreads();

        // ---- build masked x2 [32][64]; thread = channel (conflict-free writes) ----
        {
            float base = (tid >= 32) ? agg2s[tid - 32] : 0.f;
#pragma unroll
            for (int tt = 0; tt < 32; tt++) {
                float val = (tid < 32) ? p2s[tt * 33 + tid] : base;
                x2s[tt * 64 + tid] = (tt < numv) ? val : 0.f;
            }
        }
        __syncthreads();

        // ---- stages 3/4 over VALID points only (2 points / iteration) ----
        float vmax = (numv < 32) ? 0.f : -3.0e38f;
        for (int t0 = 0; t0 < numv; t0 += 2) {
            const float4* r0 = (const float4*)(x2s + t0 * 64);
            const float4* r1 = (const float4*)(x2s + t0 * 64 + 64); // row<=31 always
            float a0 = 0.f, a1 = 0.f;
#pragma unroll
            for (int k = 0; k < 16; k++) {
                float4 xa = r0[k];
                a0 = fmaf(xa.x, w3r[4*k], a0);   a0 = fmaf(xa.y, w3r[4*k+1], a0);
                a0 = fmaf(xa.z, w3r[4*k+2], a0); a0 = fmaf(xa.w, w3r[4*k+3], a0);
                float4 xb = r1[k];
                a1 = fmaf(xb.x, w3r[4*k], a1);   a1 = fmaf(xb.y, w3r[4*k+1], a1);
                a1 = fmaf(xb.z, w3r[4*k+2], a1); a1 = fmaf(xb.w, w3r[4*k+3], a1);
            }
            x3s[tid]      = mish(fmaf(a0, s3, o3));
            x3s[64 + tid] = mish(fmaf(a1, s3, o3));
            __syncthreads();
            float b0 = 0.f, b1 = 0.f;
#pragma unroll
            for (int k = 0; k < 16; k++) {
                float4 xa = ((const float4*)x3s)[k];
                b0 = fmaf(xa.x, w4r[4*k], b0);   b0 = fmaf(xa.y, w4r[4*k+1], b0);
                b0 = fmaf(xa.z, w4r[4*k+2], b0); b0 = fmaf(xa.w, w4r[4*k+3], b0);
                float4 xb = ((const float4*)(x3s + 64))[k];
                b1 = fmaf(xb.x, w4r[4*k], b1);   b1 = fmaf(xb.y, w4r[4*k+1], b1);
                b1 = fmaf(xb.z, w4r[4*k+2], b1); b1 = fmaf(xb.w, w4r[4*k+3], b1);
            }
            float x40 = mish(fmaf(b0, s4, o4)) + x2s[t0 * 64 + tid];
            vmax = fmaxf(vmax, x40);
            if (t0 + 1 < numv) {
                float x41 = mish(fmaf(b1, s4, o4)) + x2s[t0 * 64 + 64 + tid];
                vmax = fmaxf(vmax, x41);
            }
            __syncthreads();
        }
        g_voxelwise[v * 64 + tid] = vmax;
    }
}

// ---------------- grouping ----------------
__global__ void k_count(const int* __restrict__ coors) {
    int i = blockIdx.x * blockDim.x + threadIdx.x;
    if (i >= NVOX) return;
    int cell = coors[2 * i] * BEVW + coors[2 * i + 1];
    int p = atomicAdd(&g_cellCount[cell], 1);
    if (p < CAP) g_cellMem[cell * CAP + p] = i;
}

__global__ void k_build() {
    int c = blockIdx.x * blockDim.x + threadIdx.x;
    if (c >= NCELL) return;
    int cnt = g_cellCount[c];
    if (cnt == 0) return;
    int m = min(cnt, CAP);
    int buf[CAP];
    for (int j = 0; j < m; j++) buf[j] = g_cellMem[c * CAP + j];
    for (int a = 1; a < m; a++) {           // sort ascending by voxel index
        int key = buf[a];
        int b = a - 1;
        while (b >= 0 && buf[b] > key) { buf[b + 1] = buf[b]; b--; }
        buf[b + 1] = key;
    }
    int w = atomicAdd(&g_workCount, 1);
    g_workCell[w] = c;
    int nv = min(cnt, 16);
    g_workNumv[w] = nv;
    for (int s = 0; s < 16; s++) g_workMem[w * 16 + s] = (s < nv) ? buf[s] : -1;
}

// ---------------- BFE: persistent 128-thread blocks ----------------
#define BFE_SMEM (128*129*4 + 64*16*4 + 64*17*4 + 128*4 + 128*4 + 16*4)

__global__ __launch_bounds__(128) void k_bfe(
    float* __restrict__ out,
    const float* __restrict__ W1, const float* __restrict__ bn1,
    const float* __restrict__ W2, const float* __restrict__ bn2,
    const float* __restrict__ W3, const float* __restrict__ bn3)
{
    extern __shared__ float sm[];
    float* W3s  = sm;                  // [128][129] padded
    float* x0s  = W3s + 128 * 129;     // [64][16]  (c = g*4+i, p)
    float* ys   = x0s + 64 * 16;       // [64][17]
    float* x17s = ys + 64 * 17;        // [128]
    float* x18s = x17s + 128;          // [128]
    int*   memS = (int*)(x18s + 128);  // [16]

    const int tid = threadIdx.x;

    for (int i = tid; i < 128 * 128; i += 128)
        W3s[(i >> 7) * 129 + (i & 127)] = W3[i];

    // persistent per-thread weights / bn consts
    const int g0 = tid >> 4, q0 = tid & 15;
    const int pB = tid + 128;
    const int g1 = pB >> 4, q1 = pB & 15;
    float w1a[16], w1b[16];
#pragma unroll
    for (int p = 0; p < 16; p++) {
        w1a[p] = W1[g0 * 256 + q0 * 16 + p];
        w1b[p] = W1[g1 * 256 + q1 * 16 + p];
    }
    const float s1a = bn1[g0*64 + q0]      * rsqrtf(bn1[g0*64 + 48 + q0] + EPSF);
    const float o1a = bn1[g0*64 + 16 + q0] - bn1[g0*64 + 32 + q0] * s1a;
    const float s1b = bn1[g1*64 + q1]      * rsqrtf(bn1[g1*64 + 48 + q1] + EPSF);
    const float o1b = bn1[g1*64 + 16 + q1] - bn1[g1*64 + 32 + q1] * s1b;

    const int iB = tid >> 5, gB = (tid >> 1) & 15, cB = tid & 1;
    float w2r[16];
#pragma unroll
    for (int p = 0; p < 16; p++) w2r[p] = W2[gB * 32 + cB * 16 + p];
    const float s2 = bn2[gB*8 + cB]     * rsqrtf(bn2[gB*8 + 6 + cB] + EPSF);
    const float o2 = bn2[gB*8 + 2 + cB] - bn2[gB*8 + 4 + cB] * s2;

    const float s3 = bn3[tid]       * rsqrtf(bn3[384 + tid] + EPSF);
    const float o3 = bn3[128 + tid] - bn3[256 + tid] * s3;
    __syncthreads();

    const int total = g_workCount;
    for (int w = blockIdx.x; w < total; w += gridDim.x) {
        if (tid < 16) memS[tid] = g_workMem[w * 16 + tid];
        const int cell = g_workCell[w];
        const int nv = g_workNumv[w];
        __syncthreads();

        // gather bevs: x0s[c][p] = voxelwise[mem[p]][c] (zeros for empty slots)
        for (int k = tid; k < 1024; k += 128) {
            int c = k >> 4, p = k & 15;
            int mm = memS[p];
            x0s[k] = (mm >= 0) ? g_voxelwise[mm * 64 + c] : 0.f;
        }
        __syncthreads();

        // bfe1: y[g][i][q] = mish(bn(sum_p x0[g][i][p]*W1[g][q][p])) * (q<nv)
        {
#pragma unroll
            for (int i = 0; i < 4; i++) {
                const float4* xr = (const float4*)(x0s + (g0 * 4 + i) * 16);
                float acc = 0.f;
#pragma unroll
                for (int k = 0; k < 4; k++) {
                    float4 xv = xr[k];
                    acc = fmaf(xv.x, w1a[4*k], acc);   acc = fmaf(xv.y, w1a[4*k+1], acc);
                    acc = fmaf(xv.z, w1a[4*k+2], acc); acc = fmaf(xv.w, w1a[4*k+3], acc);
                }
                float yv = mish(fmaf(acc, s1a, o1a));
                ys[(g0 * 4 + i) * 17 + q0] = (q0 < nv) ? yv : 0.f;
            }
#pragma unroll
            for (int i = 0; i < 4; i++) {
                const float4* xr = (const float4*)(x0s + (g1 * 4 + i) * 16);
                float acc = 0.f;
#pragma unroll
                for (int k = 0; k < 4; k++) {
                    float4 xv = xr[k];
                    acc = fmaf(xv.x, w1b[4*k], acc);   acc = fmaf(xv.y, w1b[4*k+1], acc);
                    acc = fmaf(xv.z, w1b[4*k+2], acc); acc = fmaf(xv.w, w1b[4*k+3], acc);
                }
                float yv = mish(fmaf(acc, s1b, o1b));
                ys[(g1 * 4 + i) * 17 + q1] = (q1 < nv) ? yv : 0.f;
            }
        }
        __syncthreads();

        // bfe2 -> x17 in torch-cat layout: x17[i*32 + g*2 + c]
        {
            const float* yr = ys + (gB * 4 + iB) * 17;
            float acc = 0.f;
#pragma unroll
            for (int p = 0; p < 16; p++) acc = fmaf(yr[p], w2r[p], acc);
            x17s[tid] = mish(fmaf(acc, s2, o2));
        }
        __syncthreads();

        // bfe3 applied twice (same weights/bn)
        {
            float acc = 0.f;
            const float* wr = W3s + tid * 129;
#pragma unroll
            for (int k = 0; k < 32; k++) {
                float4 xv = ((const float4*)x17s)[k];
                acc = fmaf(xv.x, wr[4*k], acc);   acc = fmaf(xv.y, wr[4*k+1], acc);
                acc = fmaf(xv.z, wr[4*k+2], acc); acc = fmaf(xv.w, wr[4*k+3], acc);
            }
            x18s[tid] = mish(fmaf(acc, s3, o3));
        }
        __syncthreads();
        float x19;
        {
            float acc = 0.f;
            const float* wr = W3s + tid * 129;
#pragma unroll
            for (int k = 0; k < 32; k++) {
                float4 xv = ((const float4*)x18s)[k];
                acc = fmaf(xv.x, wr[4*k], acc);   acc = fmaf(xv.y, wr[4*k+1], acc);
                acc = fmaf(xv.z, wr[4*k+2], acc); acc = fmaf(xv.w, wr[4*k+3], acc);
            }
            x19 = mish(fmaf(acc, s3, o3));
        }

        // out[ch][cx][cy]
        int cy = cell / BEVW;
        int cx = cell - cy * BEVW;
        out[tid * NCELL + cx * BEVH + cy] = x19;
        __syncthreads();
    }
}

// ---------------- launcher ----------------
extern "C" void kernel_launch(void* const* d_in, const int* in_sizes, int n_in,
                              void* d_out, int out_size) {
    const float* feat   = (const float*)d_in[0];
    const int*   coors  = (const int*)d_in[1];
    const int*   nvox   = (const int*)d_in[2];
    const float* vfe1_W = (const float*)d_in[3];
    const float* vfe1_b = (const float*)d_in[4];
    const float* vfe2_W = (const float*)d_in[5];
    const float* vfe2_b = (const float*)d_in[6];
    const float* vfe3_W = (const float*)d_in[7];
    const float* vfe3_b = (const float*)d_in[8];
    const float* vfe4_W = (const float*)d_in[9];
    const float* vfe4_b = (const float*)d_in[10];
    const float* bfe1_W = (const float*)d_in[11];
    const float* bfe1_b = (const float*)d_in[12];
    const float* bfe2_W = (const float*)d_in[13];
    const float* bfe2_b = (const float*)d_in[14];
    const float* bfe3_W = (const float*)d_in[15];
    const float* bfe3_b = (const float*)d_in[16];
    float* out = (float*)d_out;

    cudaFuncSetAttribute(k_bfe, cudaFuncAttributeMaxDynamicSharedMemorySize, BFE_SMEM);

    k_zero_out<<<4096, 256>>>((float4*)d_out, out_size / 4);
    k_zero_meta<<<(NCELL + 255) / 256, 256>>>();
    k_vfe<<<740, 64>>>(feat, nvox, vfe1_W, vfe1_b, vfe2_W, vfe2_b,
                       vfe3_W, vfe3_b, vfe4_W, vfe4_b);
    k_count<<<(NVOX + 255) / 256, 256>>>(coors);
    k_build<<<(NCELL + 255) / 256, 256>>>();
    k_bfe<<<444, 128, BFE_SMEM>>>(out, bfe1_W, bfe1_b, bfe2_W, bfe2_b,
                                  bfe3_W, bfe3_b);
}

// round 3
// speedup vs baseline: 1.2393x; 1.2393x over previous
#include <cuda_runtime.h>

#define NVOX  40000
#define BEVH  496
#define BEVW  432
#define NCELL (BEVH*BEVW)      /* 214272 */
#define CAP   32
#define EPSF  1e-5f

typedef unsigned long long ull;

// ---------------- scratch (static device memory) ----------------
__device__ float g_voxelwise[NVOX * 64];
__device__ int   g_cellCount[NCELL];
__device__ int   g_cellMem[NCELL * CAP];
__device__ int   g_workCell[NVOX];
__device__ int   g_workNumv[NVOX];
__device__ int   g_workMem[NVOX * 16];
__device__ int   g_workCount;

// ---------------- f32x2 helpers ----------------
__device__ __forceinline__ ull pk(float x, float y) {
    ull r; asm("mov.b64 %0,{%1,%2};" : "=l"(r) : "f"(x), "f"(y)); return r;
}
__device__ __forceinline__ float hsum(ull v) {
    float a, b; asm("mov.b64 {%0,%1},%2;" : "=f"(a), "=f"(b) : "l"(v)); return a + b;
}
__device__ __forceinline__ ull ffma2(ull a, ull b, ull c) {
    ull d; asm("fma.rn.f32x2 %0,%1,%2,%3;" : "=l"(d) : "l"(a), "l"(b), "l"(c)); return d;
}

__device__ __forceinline__ float mish(float y) {
    float u = __expf(fminf(y, 25.0f));
    float t = 1.0f + u;
    t = t * t;
    return y * __fdividef(t - 1.0f, t + 1.0f);
}

#define GBAR(id) asm volatile("bar.sync %0, 64;" :: "r"(id) : "memory")

// ---------------- zero kernels ----------------
__global__ void k_zero_out(float4* out, int n4) {
    int i = blockIdx.x * blockDim.x + threadIdx.x;
    int stride = gridDim.x * blockDim.x;
    float4 z = make_float4(0.f, 0.f, 0.f, 0.f);
    for (; i < n4; i += stride) out[i] = z;
}

__global__ void k_zero_meta() {
    int i = blockIdx.x * blockDim.x + threadIdx.x;
    if (i < NCELL) g_cellCount[i] = 0;
    if (i == 0) g_workCount = 0;
}

// ---------------- VFE: 256 threads = 4 groups of 64 (one voxel each) ----------------
#define VFE_COMMON 656
#define VFE_GSZ    4200
#define VFE_SMEM   ((VFE_COMMON + 4 * VFE_GSZ) * 4)

__global__ __launch_bounds__(256, 1) void k_vfe(
    const float* __restrict__ feat, const int* __restrict__ nvox,
    const float* __restrict__ W1, const float* __restrict__ bn1,
    const float* __restrict__ W2, const float* __restrict__ bn2,
    const float* __restrict__ W3, const float* __restrict__ bn3,
    const float* __restrict__ W4, const float* __restrict__ bn4)
{
    extern __shared__ float sm[];
    float* W1s = sm;           // 64
    float* W2s = sm + 64;      // 512
    float* s1s = sm + 576;     // 8
    float* o1s = sm + 584;     // 8
    float* s2s = sm + 592;     // 32
    float* o2s = sm + 624;     // 32

    const int tid = threadIdx.x;
    const int l = tid & 63;    // lane within group == output channel
    const int g = tid >> 6;    // group 0..3

    if (tid < 64) W1s[tid] = W1[tid];
    W2s[tid] = W2[tid]; W2s[tid + 256] = W2[tid + 256];
    if (tid < 8) {
        float s = bn1[tid] * rsqrtf(bn1[24 + tid] + EPSF);
        s1s[tid] = s;
        o1s[tid] = bn1[8 + tid] - bn1[16 + tid] * s;
    }
    if (tid < 32) {
        float s = bn2[tid] * rsqrtf(bn2[96 + tid] + EPSF);
        s2s[tid] = s;
        o2s[tid] = bn2[32 + tid] - bn2[64 + tid] * s;
    }

    // per-thread W3/W4 row (channel l) packed as f32x2 pairs (consecutive k)
    ull w3p[32], w4p[32];
#pragma unroll
    for (int k = 0; k < 16; k++) {
        ulonglong2 u3 = ((const ulonglong2*)(W3 + l * 64))[k];
        w3p[2 * k] = u3.x; w3p[2 * k + 1] = u3.y;
        ulonglong2 u4 = ((const ulonglong2*)(W4 + l * 64))[k];
        w4p[2 * k] = u4.x; w4p[2 * k + 1] = u4.y;
    }
    const float s3 = bn3[l] * rsqrtf(bn3[192 + l] + EPSF);
    const float o3 = bn3[64 + l] - bn3[128 + l] * s3;
    const float s4 = bn4[l] * rsqrtf(bn4[192 + l] + EPSF);
    const float o4 = bn4[64 + l] - bn4[128 + l] * s4;
    __syncthreads();

    float* gb   = sm + VFE_COMMON + g * VFE_GSZ;
    float* fs   = gb;            // 256   [32][8]
    float* p1s  = gb + 256;      // 288   [32][9]
    float* agg1 = gb + 544;      // 8
    float* p2s  = gb + 552;      // 1056  [32][33]
    float* agg2 = gb + 1608;     // 32
    float* x2s  = gb + 1640;     // 2048  [32][64]
    float* x3s  = gb + 3688;     // 512   double-buffered [2][4][64]

    const int t = l & 31, half = l >> 5;
    const int bar = g + 1;

    for (int v = blockIdx.x * 4 + g; v < NVOX; v += gridDim.x * 4) {
        ((float4*)fs)[l] = ((const float4*)(feat + (size_t)v * 256))[l];
        const int numv = nvox[v];
        GBAR(bar);

        // ---- stage 1: 8 -> 8 ----
        {
            const float* fr = fs + t * 8;
            ull f0 = *(const ull*)(fr), f1 = *(const ull*)(fr + 2);
            ull f2 = *(const ull*)(fr + 4), f3 = *(const ull*)(fr + 6);
#pragma unroll
            for (int j = 0; j < 4; j++) {
                int c = half * 4 + j;
                const float* wr = W1s + c * 8;
                ull acc = ffma2(f0, *(const ull*)wr, 0ull);
                acc = ffma2(f1, *(const ull*)(wr + 2), acc);
                acc = ffma2(f2, *(const ull*)(wr + 4), acc);
                acc = ffma2(f3, *(const ull*)(wr + 6), acc);
                p1s[t * 9 + c] = mish(fmaf(hsum(acc), s1s[c], o1s[c]));
            }
        }
        GBAR(bar);
        if (l < 8) {
            float mx = -3.0e38f;
#pragma unroll
            for (int tt = 0; tt < 32; tt++) mx = fmaxf(mx, p1s[tt * 9 + l]);
            agg1[l] = mx;
        }
        GBAR(bar);

        // ---- stage 2: 16 -> 32 ----
        {
            ull xp[8];
#pragma unroll
            for (int i = 0; i < 4; i++) xp[i] = pk(p1s[t * 9 + 2 * i], p1s[t * 9 + 2 * i + 1]);
#pragma unroll
            for (int i = 0; i < 4; i++) xp[4 + i] = *(const ull*)(agg1 + 2 * i);
#pragma unroll
            for (int j = 0; j < 16; j++) {
                int c = half * 16 + j;
                const ull* wr = (const ull*)(W2s + c * 16);
                ull acc = ffma2(xp[0], wr[0], 0ull);
#pragma unroll
                for (int i = 1; i < 8; i++) acc = ffma2(xp[i], wr[i], acc);
                p2s[t * 33 + c] = mish(fmaf(hsum(acc), s2s[c], o2s[c]));
            }
        }
        GBAR(bar);
        if (l < 32) {
            float mx = -3.0e38f;
#pragma unroll
            for (int tt = 0; tt < 32; tt++) mx = fmaxf(mx, p2s[tt * 33 + l]);
            agg2[l] = mx;
        }
        GBAR(bar);

        // ---- masked x2 [32][64] ----
        {
            float base = (l >= 32) ? agg2[l - 32] : 0.f;
#pragma unroll
            for (int tt = 0; tt < 32; tt++) {
                float val = (l < 32) ? p2s[tt * 33 + l] : base;
                x2s[tt * 64 + l] = (tt < numv) ? val : 0.f;
            }
        }
        GBAR(bar);

        // ---- stages 3/4 over valid points, 4 points/iter, f32x2 ----
        float vmax = (numv == 32) ? -3.0e38f : 0.f;
        int buf = 0;
        for (int t0 = 0; t0 < numv; t0 += 4, buf ^= 1) {
            float* x3b = x3s + buf * 256;
#pragma unroll
            for (int j = 0; j < 4; j++) {
                int r = t0 + j; if (r > 31) r = 31;   // rows >= numv are zeros
                const ulonglong2* xr = (const ulonglong2*)(x2s + r * 64);
                ull acc = 0ull;
#pragma unroll
                for (int k = 0; k < 16; k++) {
                    ulonglong2 u = xr[k];
                    acc = ffma2(u.x, w3p[2 * k], acc);
                    acc = ffma2(u.y, w3p[2 * k + 1], acc);
                }
                x3b[j * 64 + l] = mish(fmaf(hsum(acc), s3, o3));
            }
            GBAR(bar);
#pragma unroll
            for (int j = 0; j < 4; j++) {
                if (t0 + j < numv) {
                    const ulonglong2* xr = (const ulonglong2*)(x3b + j * 64);
                    ull acc = 0ull;
#pragma unroll
                    for (int k = 0; k < 16; k++) {
                        ulonglong2 u = xr[k];
                        acc = ffma2(u.x, w4p[2 * k], acc);
                        acc = ffma2(u.y, w4p[2 * k + 1], acc);
                    }
                    float x4 = mish(fmaf(hsum(acc), s4, o4)) + x2s[(t0 + j) * 64 + l];
                    vmax = fmaxf(vmax, x4);
                }
            }
        }
        GBAR(bar);
        g_voxelwise[v * 64 + l] = vmax;
    }
}

// ---------------- grouping ----------------
__global__ void k_count(const int* __restrict__ coors) {
    int i = blockIdx.x * blockDim.x + threadIdx.x;
    if (i >= NVOX) return;
    int cell = coors[2 * i] * BEVW + coors[2 * i + 1];
    int p = atomicAdd(&g_cellCount[cell], 1);
    if (p < CAP) g_cellMem[cell * CAP + p] = i;
}

__global__ void k_build() {
    int c = blockIdx.x * blockDim.x + threadIdx.x;
    if (c >= NCELL) return;
    int cnt = g_cellCount[c];
    if (cnt == 0) return;
    int m = min(cnt, CAP);
    int buf[CAP];
    for (int j = 0; j < m; j++) buf[j] = g_cellMem[c * CAP + j];
    for (int a = 1; a < m; a++) {
        int key = buf[a];
        int b = a - 1;
        while (b >= 0 && buf[b] > key) { buf[b + 1] = buf[b]; b--; }
        buf[b + 1] = key;
    }
    int w = atomicAdd(&g_workCount, 1);
    g_workCell[w] = c;
    int nv = min(cnt, 16);
    g_workNumv[w] = nv;
    for (int s = 0; s < 16; s++) g_workMem[w * 16 + s] = (s < nv) ? buf[s] : -1;
}

// ---------------- BFE: persistent 128-thread blocks, batch of 4 cells ----------------
// shared floats: W3s 128*132=16896 | x0s 4*64*18=4608 | ys 4608 | x17s 512 | x18s 512
#define BFE_SMEM (27136 * 4 + 72 * 4)

__global__ __launch_bounds__(128, 2) void k_bfe(
    float* __restrict__ out,
    const float* __restrict__ W1, const float* __restrict__ bn1,
    const float* __restrict__ W2, const float* __restrict__ bn2,
    const float* __restrict__ W3, const float* __restrict__ bn3)
{
    extern __shared__ float sm[];
    float* W3s  = sm;                 // [128][132]
    float* x0s  = sm + 16896;         // [4][64][18]
    float* ys   = sm + 21504;         // [4][64][18]
    float* x17s = sm + 26112;         // [4][128]
    float* x18s = sm + 26624;         // [4][128]
    int*   memS  = (int*)(sm + 27136); // [4][16]
    int*   cellS = memS + 64;          // [4]
    int*   nvS   = cellS + 4;          // [4]

    const int tid = threadIdx.x;

    for (int i = tid; i < 128 * 128; i += 128)
        W3s[(i >> 7) * 132 + (i & 127)] = W3[i];

    // bfe1: thread handles (g0, q0) and (g0+8, q0)
    const int g0 = tid >> 4, q0 = tid & 15;
    ull w1a[8], w1b[8];
#pragma unroll
    for (int k = 0; k < 4; k++) {
        ulonglong2 ua = ((const ulonglong2*)(W1 + g0 * 256 + q0 * 16))[k];
        w1a[2 * k] = ua.x; w1a[2 * k + 1] = ua.y;
        ulonglong2 ub = ((const ulonglong2*)(W1 + (g0 + 8) * 256 + q0 * 16))[k];
        w1b[2 * k] = ub.x; w1b[2 * k + 1] = ub.y;
    }
    const float s1a = bn1[g0*64 + q0]      * rsqrtf(bn1[g0*64 + 48 + q0] + EPSF);
    const float o1a = bn1[g0*64 + 16 + q0] - bn1[g0*64 + 32 + q0] * s1a;
    const int gx = g0 + 8;
    const float s1b = bn1[gx*64 + q0]      * rsqrtf(bn1[gx*64 + 48 + q0] + EPSF);
    const float o1b = bn1[gx*64 + 16 + q0] - bn1[gx*64 + 32 + q0] * s1b;

    const int iB = tid >> 5, gB = (tid >> 1) & 15, cB = tid & 1;
    ull w2p[8];
#pragma unroll
    for (int k = 0; k < 4; k++) {
        ulonglong2 u = ((const ulonglong2*)(W2 + gB * 32 + cB * 16))[k];
        w2p[2 * k] = u.x; w2p[2 * k + 1] = u.y;
    }
    const float s2 = bn2[gB*8 + cB]     * rsqrtf(bn2[gB*8 + 6 + cB] + EPSF);
    const float o2 = bn2[gB*8 + 2 + cB] - bn2[gB*8 + 4 + cB] * s2;

    const float s3 = bn3[tid]       * rsqrtf(bn3[384 + tid] + EPSF);
    const float o3 = bn3[128 + tid] - bn3[256 + tid] * s3;
    __syncthreads();

    const int M = g_workCount;
    const int nb = (M + 3) >> 2;
    for (int batch = blockIdx.x; batch < nb; batch += gridDim.x) {
        if (tid < 64) {
            int w = batch * 4 + (tid >> 4);
            memS[tid] = (w < M) ? g_workMem[w * 16 + (tid & 15)] : -1;
        }
        if (tid < 4) {
            int w = batch * 4 + tid;
            cellS[tid] = (w < M) ? g_workCell[w] : -1;
            nvS[tid]   = (w < M) ? g_workNumv[w] : 0;
        }
        __syncthreads();

        // gather: coalesced over channel
#pragma unroll
        for (int i = 0; i < 32; i++) {
            int idx = tid + i * 128;
            int c = idx & 63, p = (idx >> 6) & 15, b = idx >> 10;
            int mm = memS[b * 16 + p];
            x0s[b * 1152 + c * 18 + p] = (mm >= 0) ? g_voxelwise[mm * 64 + c] : 0.f;
        }
        __syncthreads();

        // bfe1
#pragma unroll
        for (int b = 0; b < 4; b++) {
            const int nv = nvS[b];
            const float* x0b = x0s + b * 1152;
            float* yb = ys + b * 1152;
#pragma unroll
            for (int i = 0; i < 4; i++) {
                const float* row = x0b + (g0 * 4 + i) * 18;
                ull acc = 0ull;
#pragma unroll
                for (int kk = 0; kk < 8; kk++)
                    acc = ffma2(*(const ull*)(row + 2 * kk), w1a[kk], acc);
                float yv = mish(fmaf(hsum(acc), s1a, o1a));
                yb[(g0 * 4 + i) * 18 + q0] = (q0 < nv) ? yv : 0.f;
            }
#pragma unroll
            for (int i = 0; i < 4; i++) {
                const float* row = x0b + (gx * 4 + i) * 18;
                ull acc = 0ull;
#pragma unroll
                for (int kk = 0; kk < 8; kk++)
                    acc = ffma2(*(const ull*)(row + 2 * kk), w1b[kk], acc);
                float yv = mish(fmaf(hsum(acc), s1b, o1b));
                yb[(gx * 4 + i) * 18 + q0] = (q0 < nv) ? yv : 0.f;
            }
        }
        __syncthreads();

        // bfe2 -> x17 (torch-cat layout x17[i*32 + g*2 + c] == x17[tid])
#pragma unroll
        for (int b = 0; b < 4; b++) {
            const float* row = ys + b * 1152 + (gB * 4 + iB) * 18;
            ull acc = 0ull;
#pragma unroll
            for (int kk = 0; kk < 8; kk++)
                acc = ffma2(*(const ull*)(row + 2 * kk), w2p[kk], acc);
            x17s[b * 128 + tid] = mish(fmaf(hsum(acc), s2, o2));
        }
        __syncthreads();

        // bfe3 pass 1 (x17 -> x18), W chunks in regs reused across 4 cells
        const ulonglong2* wr = (const ulonglong2*)(W3s + tid * 132);
        {
            ull acc[4] = {0ull, 0ull, 0ull, 0ull};
#pragma unroll
            for (int kc = 0; kc < 8; kc++) {
                ulonglong2 wa = wr[kc*4], wb = wr[kc*4+1], wc = wr[kc*4+2], wd = wr[kc*4+3];
#pragma unroll
                for (int b = 0; b < 4; b++) {
                    const ulonglong2* xr = (const ulonglong2*)(x17s + b * 128 + kc * 16);
                    ulonglong2 xa = xr[0], xb = xr[1], xc = xr[2], xd = xr[3];
                    acc[b] = ffma2(xa.x, wa.x, acc[b]); acc[b] = ffma2(xa.y, wa.y, acc[b]);
                    acc[b] = ffma2(xb.x, wb.x, acc[b]); acc[b] = ffma2(xb.y, wb.y, acc[b]);
                    acc[b] = ffma2(xc.x, wc.x, acc[b]); acc[b] = ffma2(xc.y, wc.y, acc[b]);
                    acc[b] = ffma2(xd.x, wd.x, acc[b]); acc[b] = ffma2(xd.y, wd.y, acc[b]);
                }
            }
#pragma unroll
            for (int b = 0; b < 4; b++)
                x18s[b * 128 + tid] = mish(fmaf(hsum(acc[b]), s3, o3));
        }
        __syncthreads();

        // bfe3 pass 2 (x18 -> x19) + scattered store
        {
            ull acc[4] = {0ull, 0ull, 0ull, 0ull};
#pragma unroll
            for (int kc = 0; kc < 8; kc++) {
                ulonglong2 wa = wr[kc*4], wb = wr[kc*4+1], wc = wr[kc*4+2], wd = wr[kc*4+3];
#pragma unroll
                for (int b = 0; b < 4; b++) {
                    const ulonglong2* xr = (const ulonglong2*)(x18s + b * 128 + kc * 16);
                    ulonglong2 xa = xr[0], xb = xr[1], xc = xr[2], xd = xr[3];
                    acc[b] = ffma2(xa.x, wa.x, acc[b]); acc[b] = ffma2(xa.y, wa.y, acc[b]);
                    acc[b] = ffma2(xb.x, wb.x, acc[b]); acc[b] = ffma2(xb.y, wb.y, acc[b]);
                    acc[b] = ffma2(xc.x, wc.x, acc[b]); acc[b] = ffma2(xc.y, wc.y, acc[b]);
                    acc[b] = ffma2(xd.x, wd.x, acc[b]); acc[b] = ffma2(xd.y, wd.y, acc[b]);
                }
            }
#pragma unroll
            for (int b = 0; b < 4; b++) {
                int cell = cellS[b];
                if (cell >= 0) {
                    float x19 = mish(fmaf(hsum(acc[b]), s3, o3));
                    int cy = cell / BEVW;
                    int cx = cell - cy * BEVW;
                    out[tid * NCELL + cx * BEVH + cy] = x19;
                }
            }
        }
        __syncthreads();
    }
}

// ---------------- launcher ----------------
extern "C" void kernel_launch(void* const* d_in, const int* in_sizes, int n_in,
                              void* d_out, int out_size) {
    const float* feat   = (const float*)d_in[0];
    const int*   coors  = (const int*)d_in[1];
    const int*   nvox   = (const int*)d_in[2];
    const float* vfe1_W = (const float*)d_in[3];
    const float* vfe1_b = (const float*)d_in[4];
    const float* vfe2_W = (const float*)d_in[5];
    const float* vfe2_b = (const float*)d_in[6];
    const float* vfe3_W = (const float*)d_in[7];
    const float* vfe3_b = (const float*)d_in[8];
    const float* vfe4_W = (const float*)d_in[9];
    const float* vfe4_b = (const float*)d_in[10];
    const float* bfe1_W = (const float*)d_in[11];
    const float* bfe1_b = (const float*)d_in[12];
    const float* bfe2_W = (const float*)d_in[13];
    const float* bfe2_b = (const float*)d_in[14];
    const float* bfe3_W = (const float*)d_in[15];
    const float* bfe3_b = (const float*)d_in[16];
    float* out = (float*)d_out;

    cudaFuncSetAttribute(k_vfe, cudaFuncAttributeMaxDynamicSharedMemorySize, VFE_SMEM);
    cudaFuncSetAttribute(k_bfe, cudaFuncAttributeMaxDynamicSharedMemorySize, BFE_SMEM);

    k_zero_out<<<4096, 256>>>((float4*)d_out, out_size / 4);
    k_zero_meta<<<(NCELL + 255) / 256, 256>>>();
    k_vfe<<<148, 256, VFE_SMEM>>>(feat, nvox, vfe1_W, vfe1_b, vfe2_W, vfe2_b,
                                  vfe3_W, vfe3_b, vfe4_W, vfe4_b);
    k_count<<<(NVOX + 255) / 256, 256>>>(coors);
    k_build<<<(NCELL + 255) / 256, 256>>>();
    k_bfe<<<296, 128, BFE_SMEM>>>(out, bfe1_W, bfe1_b, bfe2_W, bfe2_b,
                                  bfe3_W, bfe3_b);
}

// round 4
// speedup vs baseline: 1.3576x; 1.0955x over previous
#include <cuda_runtime.h>

#define NVOX  40000
#define BEVH  496
#define BEVW  432
#define NCELL (BEVH*BEVW)      /* 214272 */
#define CAP   32
#define EPSF  1e-5f

typedef unsigned long long ull;

// ---------------- scratch (static device memory) ----------------
__device__ float g_voxelwise[NVOX * 64];
__device__ int   g_cellCount[NCELL];
__device__ int   g_cellMem[NCELL * CAP];
__device__ int   g_workCell[NVOX];
__device__ int   g_workNumv[NVOX];
__device__ int   g_workMem[NVOX * 16];
__device__ int   g_workCount;

// ---------------- f32x2 helpers ----------------
__device__ __forceinline__ ull pk(float x, float y) {
    ull r; asm("mov.b64 %0,{%1,%2};" : "=l"(r) : "f"(x), "f"(y)); return r;
}
__device__ __forceinline__ float hsum(ull v) {
    float a, b; asm("mov.b64 {%0,%1},%2;" : "=f"(a), "=f"(b) : "l"(v)); return a + b;
}
__device__ __forceinline__ ull ffma2(ull a, ull b, ull c) {
    ull d; asm("fma.rn.f32x2 %0,%1,%2,%3;" : "=l"(d) : "l"(a), "l"(b), "l"(c)); return d;
}

__device__ __forceinline__ float mish(float y) {
    float u = __expf(fminf(y, 25.0f));
    float t = 1.0f + u;
    t = t * t;
    return y * __fdividef(t - 1.0f, t + 1.0f);
}

#define GBAR128(id) asm volatile("bar.sync %0, 128;" :: "r"(id) : "memory")

// ---------------- zero kernels ----------------
__global__ void k_zero_out(float4* out, int n4) {
    int i = blockIdx.x * blockDim.x + threadIdx.x;
    int stride = gridDim.x * blockDim.x;
    float4 z = make_float4(0.f, 0.f, 0.f, 0.f);
    for (; i < n4; i += stride) out[i] = z;
}

__global__ void k_zero_meta() {
    int i = blockIdx.x * blockDim.x + threadIdx.x;
    if (i < NCELL) g_cellCount[i] = 0;
    if (i == 0) g_workCount = 0;
}

// ---------------- VFE: 256 threads = 2 groups of 128 (one voxel each) ----------------
// Per group: lower 64 threads = stage3 (W3 row in regs), upper 64 = stage4 (W4 row),
// software-pipelined over 4-point chunks.
#define VFE_COMMON 656
#define VFE_GSZ    4200
#define VFE_SMEM   ((VFE_COMMON + 2 * VFE_GSZ) * 4)

__global__ __launch_bounds__(256, 2) void k_vfe(
    const float* __restrict__ feat, const int* __restrict__ nvox,
    const float* __restrict__ W1, const float* __restrict__ bn1,
    const float* __restrict__ W2, const float* __restrict__ bn2,
    const float* __restrict__ W3, const float* __restrict__ bn3,
    const float* __restrict__ W4, const float* __restrict__ bn4)
{
    extern __shared__ float sm[];
    float* W1s = sm;           // 64
    float* W2s = sm + 64;      // 512
    float* s1s = sm + 576;     // 8
    float* o1s = sm + 584;     // 8
    float* s2s = sm + 592;     // 32
    float* o2s = sm + 624;     // 32

    const int tid = threadIdx.x;
    const int l = tid & 127;   // lane within group
    const int g = tid >> 7;    // group 0..1

    if (tid < 64) W1s[tid] = W1[tid];
    W2s[tid] = W2[tid]; W2s[tid + 256] = W2[tid + 256];
    if (tid < 8) {
        float s = bn1[tid] * rsqrtf(bn1[24 + tid] + EPSF);
        s1s[tid] = s;
        o1s[tid] = bn1[8 + tid] - bn1[16 + tid] * s;
    }
    if (tid < 32) {
        float s = bn2[tid] * rsqrtf(bn2[96 + tid] + EPSF);
        s2s[tid] = s;
        o2s[tid] = bn2[32 + tid] - bn2[64 + tid] * s;
    }

    const bool lower = (l < 64);
    const int ch = lower ? l : (l - 64);
    // this thread's weight row (W3 for lower half, W4 for upper), packed f32x2
    ull wp[32];
    {
        const float* Wrow = (lower ? W3 : W4) + ch * 64;
#pragma unroll
        for (int k = 0; k < 16; k++) {
            ulonglong2 u = ((const ulonglong2*)Wrow)[k];
            wp[2 * k] = u.x; wp[2 * k + 1] = u.y;
        }
    }
    const float* bnp = lower ? bn3 : bn4;
    const float sS = bnp[ch] * rsqrtf(bnp[192 + ch] + EPSF);
    const float oS = bnp[64 + ch] - bnp[128 + ch] * sS;
    __syncthreads();

    float* gb   = sm + VFE_COMMON + g * VFE_GSZ;
    float* fs   = gb;            // 256   [32][8]
    float* p1s  = gb + 256;      // 288   [32][9]
    float* agg1 = gb + 544;      // 8
    float* p2s  = gb + 552;      // 1056  [32][33]
    float* agg2 = gb + 1608;     // 32
    float* x2s  = gb + 1640;     // 2048  [32][64]
    float* x3s  = gb + 3688;     // 512   double-buffered [2][4][64]

    const int t = l & 31, q = (l >> 5) & 3;
    const int bar = g + 1;
    const int vstep = gridDim.x * 2;

    int v = blockIdx.x * 2 + g;
    float2 pf = make_float2(0.f, 0.f);
    if (v < NVOX) pf = ((const float2*)(feat + (size_t)v * 256))[l];

    for (; v < NVOX; v += vstep) {
        ((float2*)fs)[l] = pf;
        const int numv = nvox[v];
        GBAR128(bar);

        // ---- stage 1: 8 -> 8, thread (t,q) computes channels q*2, q*2+1 ----
        {
            const float* fr = fs + t * 8;
            ull f0 = *(const ull*)(fr), f1 = *(const ull*)(fr + 2);
            ull f2 = *(const ull*)(fr + 4), f3 = *(const ull*)(fr + 6);
#pragma unroll
            for (int j = 0; j < 2; j++) {
                int c = q * 2 + j;
                const float* wr = W1s + c * 8;
                ull acc = ffma2(f0, *(const ull*)wr, 0ull);
                acc = ffma2(f1, *(const ull*)(wr + 2), acc);
                acc = ffma2(f2, *(const ull*)(wr + 4), acc);
                acc = ffma2(f3, *(const ull*)(wr + 6), acc);
                p1s[t * 9 + c] = mish(fmaf(hsum(acc), s1s[c], o1s[c]));
            }
        }
        GBAR128(bar);

        // prefetch next voxel's features while stages 2-4 run
        {
            int vn = v + vstep;
            if (vn < NVOX) pf = ((const float2*)(feat + (size_t)vn * 256))[l];
        }

        if (l < 8) {
            float mx = -3.0e38f;
#pragma unroll
            for (int tt = 0; tt < 32; tt++) mx = fmaxf(mx, p1s[tt * 9 + l]);
            agg1[l] = mx;
        }
        GBAR128(bar);

        // ---- stage 2: 16 -> 32, thread (t,q) computes channels q*8 .. q*8+7 ----
        {
            ull xp[8];
#pragma unroll
            for (int i = 0; i < 4; i++) xp[i] = pk(p1s[t * 9 + 2 * i], p1s[t * 9 + 2 * i + 1]);
#pragma unroll
            for (int i = 0; i < 4; i++) xp[4 + i] = *(const ull*)(agg1 + 2 * i);
#pragma unroll
            for (int j = 0; j < 8; j++) {
                int c = q * 8 + j;
                const ull* wr = (const ull*)(W2s + c * 16);
                ull acc = ffma2(xp[0], wr[0], 0ull);
#pragma unroll
                for (int i = 1; i < 8; i++) acc = ffma2(xp[i], wr[i], acc);
                p2s[t * 33 + c] = mish(fmaf(hsum(acc), s2s[c], o2s[c]));
            }
        }
        GBAR128(bar);
        if (l < 32) {
            float mx = -3.0e38f;
#pragma unroll
            for (int tt = 0; tt < 32; tt++) mx = fmaxf(mx, p2s[tt * 33 + l]);
            agg2[l] = mx;
        }
        GBAR128(bar);

        // ---- masked x2 [32][64]: thread handles channel (l&63), 16 rows ----
        {
            int c2 = l & 63, h = l >> 6;
            float base = (c2 >= 32) ? agg2[c2 - 32] : 0.f;
#pragma unroll
            for (int i = 0; i < 16; i++) {
                int rr = h * 16 + i;
                float val = (c2 < 32) ? p2s[rr * 33 + c2] : base;
                x2s[rr * 64 + c2] = (rr < numv) ? val : 0.f;
            }
        }
        GBAR128(bar);

        // ---- pipelined stages 3/4: lower computes x3[chunk it], upper x4[chunk it-1] ----
        const int nch = (numv + 3) >> 2;
        float vmax = (numv == 32) ? -3.0e38f : 0.f;
        for (int it = 0; it <= nch; ++it) {
            if (lower) {
                if (it < nch) {
                    int t0 = it * 4;
                    int nr = numv - t0; if (nr > 4) nr = 4;
                    float* x3b = x3s + (it & 1) * 256;
#pragma unroll
                    for (int j = 0; j < 4; j++) {
                        if (j < nr) {   // uniform branch
                            const ulonglong2* xr = (const ulonglong2*)(x2s + (t0 + j) * 64);
                            ull acc = 0ull;
#pragma unroll
                            for (int k = 0; k < 16; k++) {
                                ulonglong2 u = xr[k];
                                acc = ffma2(u.x, wp[2 * k], acc);
                                acc = ffma2(u.y, wp[2 * k + 1], acc);
                            }
                            x3b[j * 64 + ch] = mish(fmaf(hsum(acc), sS, oS));
                        }
                    }
                }
            } else {
                if (it >= 1) {
                    int t0 = (it - 1) * 4;
                    int nr = numv - t0; if (nr > 4) nr = 4;
                    const float* x3b = x3s + ((it - 1) & 1) * 256;
#pragma unroll
                    for (int j = 0; j < 4; j++) {
                        if (j < nr) {   // uniform branch
                            const ulonglong2* xr = (const ulonglong2*)(x3b + j * 64);
                            ull acc = 0ull;
#pragma unroll
                            for (int k = 0; k < 16; k++) {
                                ulonglong2 u = xr[k];
                                acc = ffma2(u.x, wp[2 * k], acc);
                                acc = ffma2(u.y, wp[2 * k + 1], acc);
                            }
                            float x4 = mish(fmaf(hsum(acc), sS, oS)) + x2s[(t0 + j) * 64 + ch];
                            vmax = fmaxf(vmax, x4);
                        }
                    }
                }
            }
            GBAR128(bar);
        }
        if (!lower) g_voxelwise[(size_t)v * 64 + ch] = vmax;
    }
}

// ---------------- grouping ----------------
__global__ void k_count(const int* __restrict__ coors) {
    int i = blockIdx.x * blockDim.x + threadIdx.x;
    if (i >= NVOX) return;
    int cell = coors[2 * i] * BEVW + coors[2 * i + 1];
    int p = atomicAdd(&g_cellCount[cell], 1);
    if (p < CAP) g_cellMem[cell * CAP + p] = i;
}

__global__ void k_build() {
    int c = blockIdx.x * blockDim.x + threadIdx.x;
    if (c >= NCELL) return;
    int cnt = g_cellCount[c];
    if (cnt == 0) return;
    int m = min(cnt, CAP);
    int buf[CAP];
    for (int j = 0; j < m; j++) buf[j] = g_cellMem[c * CAP + j];
    for (int a = 1; a < m; a++) {
        int key = buf[a];
        int b = a - 1;
        while (b >= 0 && buf[b] > key) { buf[b + 1] = buf[b]; b--; }
        buf[b + 1] = key;
    }
    int w = atomicAdd(&g_workCount, 1);
    g_workCell[w] = c;
    int nv = min(cnt, 16);
    g_workNumv[w] = nv;
    for (int s = 0; s < 16; s++) g_workMem[w * 16 + s] = (s < nv) ? buf[s] : -1;
}

// ---------------- BFE: persistent 128-thread blocks, batch of 4 cells ----------------
#define BFE_SMEM (27136 * 4 + 72 * 4)

__global__ __launch_bounds__(128, 2) void k_bfe(
    float* __restrict__ out,
    const float* __restrict__ W1, const float* __restrict__ bn1,
    const float* __restrict__ W2, const float* __restrict__ bn2,
    const float* __restrict__ W3, const float* __restrict__ bn3)
{
    extern __shared__ float sm[];
    float* W3s  = sm;                 // [128][132]
    float* x0s  = sm + 16896;         // [4][64][18]
    float* ys   = sm + 21504;         // [4][64][18]
    float* x17s = sm + 26112;         // [4][128]
    float* x18s = sm + 26624;         // [4][128]
    int*   memS  = (int*)(sm + 27136); // [4][16]
    int*   cellS = memS + 64;          // [4]
    int*   nvS   = cellS + 4;          // [4]

    const int tid = threadIdx.x;

    for (int i = tid; i < 128 * 128; i += 128)
        W3s[(i >> 7) * 132 + (i & 127)] = W3[i];

    const int g0 = tid >> 4, q0 = tid & 15;
    ull w1a[8], w1b[8];
#pragma unroll
    for (int k = 0; k < 4; k++) {
        ulonglong2 ua = ((const ulonglong2*)(W1 + g0 * 256 + q0 * 16))[k];
        w1a[2 * k] = ua.x; w1a[2 * k + 1] = ua.y;
        ulonglong2 ub = ((const ulonglong2*)(W1 + (g0 + 8) * 256 + q0 * 16))[k];
        w1b[2 * k] = ub.x; w1b[2 * k + 1] = ub.y;
    }
    const float s1a = bn1[g0*64 + q0]      * rsqrtf(bn1[g0*64 + 48 + q0] + EPSF);
    const float o1a = bn1[g0*64 + 16 + q0] - bn1[g0*64 + 32 + q0] * s1a;
    const int gx = g0 + 8;
    const float s1b = bn1[gx*64 + q0]      * rsqrtf(bn1[gx*64 + 48 + q0] + EPSF);
    const float o1b = bn1[gx*64 + 16 + q0] - bn1[gx*64 + 32 + q0] * s1b;

    const int iB = tid >> 5, gB = (tid >> 1) & 15, cB = tid & 1;
    ull w2p[8];
#pragma unroll
    for (int k = 0; k < 4; k++) {
        ulonglong2 u = ((const ulonglong2*)(W2 + gB * 32 + cB * 16))[k];
        w2p[2 * k] = u.x; w2p[2 * k + 1] = u.y;
    }
    const float s2 = bn2[gB*8 + cB]     * rsqrtf(bn2[gB*8 + 6 + cB] + EPSF);
    const float o2 = bn2[gB*8 + 2 + cB] - bn2[gB*8 + 4 + cB] * s2;

    const float s3 = bn3[tid]       * rsqrtf(bn3[384 + tid] + EPSF);
    const float o3 = bn3[128 + tid] - bn3[256 + tid] * s3;
    __syncthreads();

    const int M = g_workCount;
    const int nb = (M + 3) >> 2;
    for (int batch = blockIdx.x; batch < nb; batch += gridDim.x) {
        if (tid < 64) {
            int w = batch * 4 + (tid >> 4);
            memS[tid] = (w < M) ? g_workMem[w * 16 + (tid & 15)] : -1;
        }
        if (tid < 4) {
            int w = batch * 4 + tid;
            cellS[tid] = (w < M) ? g_workCell[w] : -1;
            nvS[tid]   = (w < M) ? g_workNumv[w] : 0;
        }
        __syncthreads();

#pragma unroll
        for (int i = 0; i < 32; i++) {
            int idx = tid + i * 128;
            int c = idx & 63, p = (idx >> 6) & 15, b = idx >> 10;
            int mm = memS[b * 16 + p];
            x0s[b * 1152 + c * 18 + p] = (mm >= 0) ? g_voxelwise[mm * 64 + c] : 0.f;
        }
        __syncthreads();

        // bfe1
#pragma unroll
        for (int b = 0; b < 4; b++) {
            const int nv = nvS[b];
            const float* x0b = x0s + b * 1152;
            float* yb = ys + b * 1152;
#pragma unroll
            for (int i = 0; i < 4; i++) {
                const float* row = x0b + (g0 * 4 + i) * 18;
                ull acc = 0ull;
#pragma unroll
                for (int kk = 0; kk < 8; kk++)
                    acc = ffma2(*(const ull*)(row + 2 * kk), w1a[kk], acc);
                float yv = mish(fmaf(hsum(acc), s1a, o1a));
                yb[(g0 * 4 + i) * 18 + q0] = (q0 < nv) ? yv : 0.f;
            }
#pragma unroll
            for (int i = 0; i < 4; i++) {
                const float* row = x0b + (gx * 4 + i) * 18;
                ull acc = 0ull;
#pragma unroll
                for (int kk = 0; kk < 8; kk++)
                    acc = ffma2(*(const ull*)(row + 2 * kk), w1b[kk], acc);
                float yv = mish(fmaf(hsum(acc), s1b, o1b));
                yb[(gx * 4 + i) * 18 + q0] = (q0 < nv) ? yv : 0.f;
            }
        }
        __syncthreads();

        // bfe2 -> x17 (torch-cat layout)
#pragma unroll
        for (int b = 0; b < 4; b++) {
            const float* row = ys + b * 1152 + (gB * 4 + iB) * 18;
            ull acc = 0ull;
#pragma unroll
            for (int kk = 0; kk < 8; kk++)
                acc = ffma2(*(const ull*)(row + 2 * kk), w2p[kk], acc);
            x17s[b * 128 + tid] = mish(fmaf(hsum(acc), s2, o2));
        }
        __syncthreads();

        const ulonglong2* wr = (const ulonglong2*)(W3s + tid * 132);
        // bfe3 pass 1
        {
            ull acc[4] = {0ull, 0ull, 0ull, 0ull};
#pragma unroll
            for (int kc = 0; kc < 8; kc++) {
                ulonglong2 wa = wr[kc*4], wb = wr[kc*4+1], wc = wr[kc*4+2], wd = wr[kc*4+3];
#pragma unroll
                for (int b = 0; b < 4; b++) {
                    const ulonglong2* xr = (const ulonglong2*)(x17s + b * 128 + kc * 16);
                    ulonglong2 xa = xr[0], xb = xr[1], xc = xr[2], xd = xr[3];
                    acc[b] = ffma2(xa.x, wa.x, acc[b]); acc[b] = ffma2(xa.y, wa.y, acc[b]);
                    acc[b] = ffma2(xb.x, wb.x, acc[b]); acc[b] = ffma2(xb.y, wb.y, acc[b]);
                    acc[b] = ffma2(xc.x, wc.x, acc[b]); acc[b] = ffma2(xc.y, wc.y, acc[b]);
                    acc[b] = ffma2(xd.x, wd.x, acc[b]); acc[b] = ffma2(xd.y, wd.y, acc[b]);
                }
            }
#pragma unroll
            for (int b = 0; b < 4; b++)
                x18s[b * 128 + tid] = mish(fmaf(hsum(acc[b]), s3, o3));
        }
        __syncthreads();

        // bfe3 pass 2 + scattered store
        {
            ull acc[4] = {0ull, 0ull, 0ull, 0ull};
#pragma unroll
            for (int kc = 0; kc < 8; kc++) {
                ulonglong2 wa = wr[kc*4], wb = wr[kc*4+1], wc = wr[kc*4+2], wd = wr[kc*4+3];
#pragma unroll
                for (int b = 0; b < 4; b++) {
                    const ulonglong2* xr = (const ulonglong2*)(x18s + b * 128 + kc * 16);
                    ulonglong2 xa = xr[0], xb = xr[1], xc = xr[2], xd = xr[3];
                    acc[b] = ffma2(xa.x, wa.x, acc[b]); acc[b] = ffma2(xa.y, wa.y, acc[b]);
                    acc[b] = ffma2(xb.x, wb.x, acc[b]); acc[b] = ffma2(xb.y, wb.y, acc[b]);
                    acc[b] = ffma2(xc.x, wc.x, acc[b]); acc[b] = ffma2(xc.y, wc.y, acc[b]);
                    acc[b] = ffma2(xd.x, wd.x, acc[b]); acc[b] = ffma2(xd.y, wd.y, acc[b]);
                }
            }
#pragma unroll
            for (int b = 0; b < 4; b++) {
                int cell = cellS[b];
                if (cell >= 0) {
                    float x19 = mish(fmaf(hsum(acc[b]), s3, o3));
                    int cy = cell / BEVW;
                    int cx = cell - cy * BEVW;
                    out[tid * NCELL + cx * BEVH + cy] = x19;
                }
            }
        }
        __syncthreads();
    }
}

// ---------------- launcher ----------------
extern "C" void kernel_launch(void* const* d_in, const int* in_sizes, int n_in,
                              void* d_out, int out_size) {
    const float* feat   = (const float*)d_in[0];
    const int*   coors  = (const int*)d_in[1];
    const int*   nvox   = (const int*)d_in[2];
    const float* vfe1_W = (const float*)d_in[3];
    const float* vfe1_b = (const float*)d_in[4];
    const float* vfe2_W = (const float*)d_in[5];
    const float* vfe2_b = (const float*)d_in[6];
    const float* vfe3_W = (const float*)d_in[7];
    const float* vfe3_b = (const float*)d_in[8];
    const float* vfe4_W = (const float*)d_in[9];
    const float* vfe4_b = (const float*)d_in[10];
    const float* bfe1_W = (const float*)d_in[11];
    const float* bfe1_b = (const float*)d_in[12];
    const float* bfe2_W = (const float*)d_in[13];
    const float* bfe2_b = (const float*)d_in[14];
    const float* bfe3_W = (const float*)d_in[15];
    const float* bfe3_b = (const float*)d_in[16];
    float* out = (float*)d_out;

    cudaFuncSetAttribute(k_vfe, cudaFuncAttributeMaxDynamicSharedMemorySize, VFE_SMEM);
    cudaFuncSetAttribute(k_bfe, cudaFuncAttributeMaxDynamicSharedMemorySize, BFE_SMEM);

    // Order chosen so launch index 3 (the one ncu captures) is k_vfe.
    k_zero_meta<<<(NCELL + 255) / 256, 256>>>();
    k_count<<<(NVOX + 255) / 256, 256>>>(coors);
    k_build<<<(NCELL + 255) / 256, 256>>>();
    k_vfe<<<296, 256, VFE_SMEM>>>(feat, nvox, vfe1_W, vfe1_b, vfe2_W, vfe2_b,
                                  vfe3_W, vfe3_b, vfe4_W, vfe4_b);
    k_zero_out<<<4096, 256>>>((float4*)d_out, out_size / 4);
    k_bfe<<<296, 128, BFE_SMEM>>>(out, bfe1_W, bfe1_b, bfe2_W, bfe2_b,
                                  bfe3_W, bfe3_b);
}

// round 5
// speedup vs baseline: 1.3621x; 1.0033x over previous
#include <cuda_runtime.h>

#define NVOX  40000
#define BEVH  496
#define BEVW  432
#define NCELL (BEVH*BEVW)      /* 214272 */
#define CAP   32
#define EPSF  1e-5f

typedef unsigned long long ull;

// ---------------- scratch (static device memory) ----------------
__device__ float g_voxelwise[NVOX * 64];
__device__ int   g_cellCount[NCELL];
__device__ int   g_cellMem[NCELL * CAP];
__device__ int   g_workCell[NVOX];
__device__ int   g_workNumv[NVOX];
__device__ int   g_workMem[NVOX * 16];
__device__ int   g_workCount;

// ---------------- f32x2 helpers ----------------
__device__ __forceinline__ ull pk(float x, float y) {
    ull r; asm("mov.b64 %0,{%1,%2};" : "=l"(r) : "f"(x), "f"(y)); return r;
}
__device__ __forceinline__ float hsum(ull v) {
    float a, b; asm("mov.b64 {%0,%1},%2;" : "=f"(a), "=f"(b) : "l"(v)); return a + b;
}
__device__ __forceinline__ ull ffma2(ull a, ull b, ull c) {
    ull d; asm("fma.rn.f32x2 %0,%1,%2,%3;" : "=l"(d) : "l"(a), "l"(b), "l"(c)); return d;
}

__device__ __forceinline__ float mish(float y) {
    float u = __expf(fminf(y, 25.0f));
    float t = 1.0f + u;
    t = t * t;
    return y * __fdividef(t - 1.0f, t + 1.0f);
}

#define GBAR128(id) asm volatile("bar.sync %0, 128;" :: "r"(id) : "memory")

// ---------------- zero kernels ----------------
__global__ void k_zero_out(float4* out, int n4) {
    int i = blockIdx.x * blockDim.x + threadIdx.x;
    int stride = gridDim.x * blockDim.x;
    float4 z = make_float4(0.f, 0.f, 0.f, 0.f);
    for (; i < n4; i += stride) out[i] = z;
}

__global__ void k_zero_meta() {
    int i = blockIdx.x * blockDim.x + threadIdx.x;
    if (i < NCELL) g_cellCount[i] = 0;
    if (i == 0) g_workCount = 0;
}

// ---------------- VFE: 256 threads = 2 groups of 128 (one voxel each) ----------------
// Per group: lower 64 threads = stage3 (W3 row in regs), upper 64 = stage4 (W4 row),
// software-pipelined over 4-point chunks.
#define VFE_COMMON 656
#define VFE_GSZ    4200
#define VFE_SMEM   ((VFE_COMMON + 2 * VFE_GSZ) * 4)

__global__ __launch_bounds__(256, 2) void k_vfe(
    const float* __restrict__ feat, const int* __restrict__ nvox,
    const float* __restrict__ W1, const float* __restrict__ bn1,
    const float* __restrict__ W2, const float* __restrict__ bn2,
    const float* __restrict__ W3, const float* __restrict__ bn3,
    const float* __restrict__ W4, const float* __restrict__ bn4)
{
    extern __shared__ float sm[];
    float* W1s = sm;           // 64
    float* W2s = sm + 64;      // 512
    float* s1s = sm + 576;     // 8
    float* o1s = sm + 584;     // 8
    float* s2s = sm + 592;     // 32
    float* o2s = sm + 624;     // 32

    const int tid = threadIdx.x;
    const int l = tid & 127;   // lane within group
    const int g = tid >> 7;    // group 0..1

    if (tid < 64) W1s[tid] = W1[tid];
    W2s[tid] = W2[tid]; W2s[tid + 256] = W2[tid + 256];
    if (tid < 8) {
        float s = bn1[tid] * rsqrtf(bn1[24 + tid] + EPSF);
        s1s[tid] = s;
        o1s[tid] = bn1[8 + tid] - bn1[16 + tid] * s;
    }
    if (tid < 32) {
        float s = bn2[tid] * rsqrtf(bn2[96 + tid] + EPSF);
        s2s[tid] = s;
        o2s[tid] = bn2[32 + tid] - bn2[64 + tid] * s;
    }

    const bool lower = (l < 64);
    const int ch = lower ? l : (l - 64);
    // this thread's weight row (W3 for lower half, W4 for upper), packed f32x2
    ull wp[32];
    {
        const float* Wrow = (lower ? W3 : W4) + ch * 64;
#pragma unroll
        for (int k = 0; k < 16; k++) {
            ulonglong2 u = ((const ulonglong2*)Wrow)[k];
            wp[2 * k] = u.x; wp[2 * k + 1] = u.y;
        }
    }
    const float* bnp = lower ? bn3 : bn4;
    const float sS = bnp[ch] * rsqrtf(bnp[192 + ch] + EPSF);
    const float oS = bnp[64 + ch] - bnp[128 + ch] * sS;
    __syncthreads();

    float* gb   = sm + VFE_COMMON + g * VFE_GSZ;
    float* fs   = gb;            // 256   [32][8]
    float* p1s  = gb + 256;      // 288   [32][9]
    float* agg1 = gb + 544;      // 8
    float* p2s  = gb + 552;      // 1056  [32][33]
    float* agg2 = gb + 1608;     // 32
    float* x2s  = gb + 1640;     // 2048  [32][64]
    float* x3s  = gb + 3688;     // 512   double-buffered [2][4][64]

    const int t = l & 31, q = (l >> 5) & 3;
    const int bar = g + 1;
    const int vstep = gridDim.x * 2;

    int v = blockIdx.x * 2 + g;
    float2 pf = make_float2(0.f, 0.f);
    if (v < NVOX) pf = ((const float2*)(feat + (size_t)v * 256))[l];

    for (; v < NVOX; v += vstep) {
        ((float2*)fs)[l] = pf;
        const int numv = nvox[v];
        GBAR128(bar);

        // ---- stage 1: 8 -> 8, thread (t,q) computes channels q*2, q*2+1 ----
        {
            const float* fr = fs + t * 8;
            ull f0 = *(const ull*)(fr), f1 = *(const ull*)(fr + 2);
            ull f2 = *(const ull*)(fr + 4), f3 = *(const ull*)(fr + 6);
#pragma unroll
            for (int j = 0; j < 2; j++) {
                int c = q * 2 + j;
                const float* wr = W1s + c * 8;
                ull acc = ffma2(f0, *(const ull*)wr, 0ull);
                acc = ffma2(f1, *(const ull*)(wr + 2), acc);
                acc = ffma2(f2, *(const ull*)(wr + 4), acc);
                acc = ffma2(f3, *(const ull*)(wr + 6), acc);
                p1s[t * 9 + c] = mish(fmaf(hsum(acc), s1s[c], o1s[c]));
            }
        }
        GBAR128(bar);

        // prefetch next voxel's features while stages 2-4 run
        {
            int vn = v + vstep;
            if (vn < NVOX) pf = ((const float2*)(feat + (size_t)vn * 256))[l];
        }

        if (l < 8) {
            float mx = -3.0e38f;
#pragma unroll
            for (int tt = 0; tt < 32; tt++) mx = fmaxf(mx, p1s[tt * 9 + l]);
            agg1[l] = mx;
        }
        GBAR128(bar);

        // ---- stage 2: 16 -> 32, thread (t,q) computes channels q*8 .. q*8+7 ----
        {
            ull xp[8];
#pragma unroll
            for (int i = 0; i < 4; i++) xp[i] = pk(p1s[t * 9 + 2 * i], p1s[t * 9 + 2 * i + 1]);
#pragma unroll
            for (int i = 0; i < 4; i++) xp[4 + i] = *(const ull*)(agg1 + 2 * i);
#pragma unroll
            for (int j = 0; j < 8; j++) {
                int c = q * 8 + j;
                const ull* wr = (const ull*)(W2s + c * 16);
                ull acc = ffma2(xp[0], wr[0], 0ull);
#pragma unroll
                for (int i = 1; i < 8; i++) acc = ffma2(xp[i], wr[i], acc);
                p2s[t * 33 + c] = mish(fmaf(hsum(acc), s2s[c], o2s[c]));
            }
        }
        GBAR128(bar);
        if (l < 32) {
            float mx = -3.0e38f;
#pragma unroll
            for (int tt = 0; tt < 32; tt++) mx = fmaxf(mx, p2s[tt * 33 + l]);
            agg2[l] = mx;
        }
        GBAR128(bar);

        // ---- masked x2 [32][64]: thread handles channel (l&63), 16 rows ----
        {
            int c2 = l & 63, h = l >> 6;
            float base = (c2 >= 32) ? agg2[c2 - 32] : 0.f;
#pragma unroll
            for (int i = 0; i < 16; i++) {
                int rr = h * 16 + i;
                float val = (c2 < 32) ? p2s[rr * 33 + c2] : base;
                x2s[rr * 64 + c2] = (rr < numv) ? val : 0.f;
            }
        }
        GBAR128(bar);

        // ---- pipelined stages 3/4: lower computes x3[chunk it], upper x4[chunk it-1] ----
        const int nch = (numv + 3) >> 2;
        float vmax = (numv == 32) ? -3.0e38f : 0.f;
        for (int it = 0; it <= nch; ++it) {
            if (lower) {
                if (it < nch) {
                    int t0 = it * 4;
                    int nr = numv - t0; if (nr > 4) nr = 4;
                    float* x3b = x3s + (it & 1) * 256;
#pragma unroll
                    for (int j = 0; j < 4; j++) {
                        if (j < nr) {   // uniform branch
                            const ulonglong2* xr = (const ulonglong2*)(x2s + (t0 + j) * 64);
                            ull acc = 0ull;
#pragma unroll
                            for (int k = 0; k < 16; k++) {
                                ulonglong2 u = xr[k];
                                acc = ffma2(u.x, wp[2 * k], acc);
                                acc = ffma2(u.y, wp[2 * k + 1], acc);
                            }
                            x3b[j * 64 + ch] = mish(fmaf(hsum(acc), sS, oS));
                        }
                    }
                }
            } else {
                if (it >= 1) {
                    int t0 = (it - 1) * 4;
                    int nr = numv - t0; if (nr > 4) nr = 4;
                    const float* x3b = x3s + ((it - 1) & 1) * 256;
#pragma unroll
                    for (int j = 0; j < 4; j++) {
                        if (j < nr) {   // uniform branch
                            const ulonglong2* xr = (const ulonglong2*)(x3b + j * 64);
                            ull acc = 0ull;
#pragma unroll
                            for (int k = 0; k < 16; k++) {
                                ulonglong2 u = xr[k];
                                acc = ffma2(u.x, wp[2 * k], acc);
                                acc = ffma2(u.y, wp[2 * k + 1], acc);
                            }
                            float x4 = mish(fmaf(hsum(acc), sS, oS)) + x2s[(t0 + j) * 64 + ch];
                            vmax = fmaxf(vmax, x4);
                        }
                    }
                }
            }
            GBAR128(bar);
        }
        if (!lower) g_voxelwise[(size_t)v * 64 + ch] = vmax;
    }
}

// ---------------- grouping ----------------
__global__ void k_count(const int* __restrict__ coors) {
    int i = blockIdx.x * blockDim.x + threadIdx.x;
    if (i >= NVOX) return;
    int cell = coors[2 * i] * BEVW + coors[2 * i + 1];
    int p = atomicAdd(&g_cellCount[cell], 1);
    if (p < CAP) g_cellMem[cell * CAP + p] = i;
}

__global__ void k_build() {
    int c = blockIdx.x * blockDim.x + threadIdx.x;
    if (c >= NCELL) return;
    int cnt = g_cellCount[c];
    if (cnt == 0) return;
    int m = min(cnt, CAP);
    int buf[CAP];
    for (int j = 0; j < m; j++) buf[j] = g_cellMem[c * CAP + j];
    for (int a = 1; a < m; a++) {
        int key = buf[a];
        int b = a - 1;
        while (b >= 0 && buf[b] > key) { buf[b + 1] = buf[b]; b--; }
        buf[b + 1] = key;
    }
    int w = atomicAdd(&g_workCount, 1);
    g_workCell[w] = c;
    int nv = min(cnt, 16);
    g_workNumv[w] = nv;
    for (int s = 0; s < 16; s++) g_workMem[w * 16 + s] = (s < nv) ? buf[s] : -1;
}

// ---------------- BFE: persistent 128-thread blocks, batch of 4 cells ----------------
#define BFE_SMEM (27136 * 4 + 72 * 4)

__global__ __launch_bounds__(128, 2) void k_bfe(
    float* __restrict__ out,
    const float* __restrict__ W1, const float* __restrict__ bn1,
    const float* __restrict__ W2, const float* __restrict__ bn2,
    const float* __restrict__ W3, const float* __restrict__ bn3)
{
    extern __shared__ float sm[];
    float* W3s  = sm;                 // [128][132]
    float* x0s  = sm + 16896;         // [4][64][18]
    float* ys   = sm + 21504;         // [4][64][18]
    float* x17s = sm + 26112;         // [4][128]
    float* x18s = sm + 26624;         // [4][128]
    int*   memS  = (int*)(sm + 27136); // [4][16]
    int*   cellS = memS + 64;          // [4]
    int*   nvS   = cellS + 4;          // [4]

    const int tid = threadIdx.x;

    for (int i = tid; i < 128 * 128; i += 128)
        W3s[(i >> 7) * 132 + (i & 127)] = W3[i];

    const int g0 = tid >> 4, q0 = tid & 15;
    ull w1a[8], w1b[8];
#pragma unroll
    for (int k = 0; k < 4; k++) {
        ulonglong2 ua = ((const ulonglong2*)(W1 + g0 * 256 + q0 * 16))[k];
        w1a[2 * k] = ua.x; w1a[2 * k + 1] = ua.y;
        ulonglong2 ub = ((const ulonglong2*)(W1 + (g0 + 8) * 256 + q0 * 16))[k];
        w1b[2 * k] = ub.x; w1b[2 * k + 1] = ub.y;
    }
    const float s1a = bn1[g0*64 + q0]      * rsqrtf(bn1[g0*64 + 48 + q0] + EPSF);
    const float o1a = bn1[g0*64 + 16 + q0] - bn1[g0*64 + 32 + q0] * s1a;
    const int gx = g0 + 8;
    const float s1b = bn1[gx*64 + q0]      * rsqrtf(bn1[gx*64 + 48 + q0] + EPSF);
    const float o1b = bn1[gx*64 + 16 + q0] - bn1[gx*64 + 32 + q0] * s1b;

    const int iB = tid >> 5, gB = (tid >> 1) & 15, cB = tid & 1;
    ull w2p[8];
#pragma unroll
    for (int k = 0; k < 4; k++) {
        ulonglong2 u = ((const ulonglong2*)(W2 + gB * 32 + cB * 16))[k];
        w2p[2 * k] = u.x; w2p[2 * k + 1] = u.y;
    }
    const float s2 = bn2[gB*8 + cB]     * rsqrtf(bn2[gB*8 + 6 + cB] + EPSF);
    const float o2 = bn2[gB*8 + 2 + cB] - bn2[gB*8 + 4 + cB] * s2;

    const float s3 = bn3[tid]       * rsqrtf(bn3[384 + tid] + EPSF);
    const float o3 = bn3[128 + tid] - bn3[256 + tid] * s3;
    __syncthreads();

    const int M = g_workCount;
    const int nb = (M + 3) >> 2;
    for (int batch = blockIdx.x; batch < nb; batch += gridDim.x) {
        if (tid < 64) {
            int w = batch * 4 + (tid >> 4);
            memS[tid] = (w < M) ? g_workMem[w * 16 + (tid & 15)] : -1;
        }
        if (tid < 4) {
            int w = batch * 4 + tid;
            cellS[tid] = (w < M) ? g_workCell[w] : -1;
            nvS[tid]   = (w < M) ? g_workNumv[w] : 0;
        }
        __syncthreads();

#pragma unroll
        for (int i = 0; i < 32; i++) {
            int idx = tid + i * 128;
            int c = idx & 63, p = (idx >> 6) & 15, b = idx >> 10;
            int mm = memS[b * 16 + p];
            x0s[b * 1152 + c * 18 + p] = (mm >= 0) ? g_voxelwise[mm * 64 + c] : 0.f;
        }
        __syncthreads();

        // bfe1
#pragma unroll
        for (int b = 0; b < 4; b++) {
            const int nv = nvS[b];
            const float* x0b = x0s + b * 1152;
            float* yb = ys + b * 1152;
#pragma unroll
            for (int i = 0; i < 4; i++) {
                const float* row = x0b + (g0 * 4 + i) * 18;
                ull acc = 0ull;
#pragma unroll
                for (int kk = 0; kk < 8; kk++)
                    acc = ffma2(*(const ull*)(row + 2 * kk), w1a[kk], acc);
                float yv = mish(fmaf(hsum(acc), s1a, o1a));
                yb[(g0 * 4 + i) * 18 + q0] = (q0 < nv) ? yv : 0.f;
            }
#pragma unroll
            for (int i = 0; i < 4; i++) {
                const float* row = x0b + (gx * 4 + i) * 18;
                ull acc = 0ull;
#pragma unroll
                for (int kk = 0; kk < 8; kk++)
                    acc = ffma2(*(const ull*)(row + 2 * kk), w1b[kk], acc);
                float yv = mish(fmaf(hsum(acc), s1b, o1b));
                yb[(gx * 4 + i) * 18 + q0] = (q0 < nv) ? yv : 0.f;
            }
        }
        __syncthreads();

        // bfe2 -> x17 (torch-cat layout)
#pragma unroll
        for (int b = 0; b < 4; b++) {
            const float* row = ys + b * 1152 + (gB * 4 + iB) * 18;
            ull acc = 0ull;
#pragma unroll
            for (int kk = 0; kk < 8; kk++)
                acc = ffma2(*(const ull*)(row + 2 * kk), w2p[kk], acc);
            x17s[b * 128 + tid] = mish(fmaf(hsum(acc), s2, o2));
        }
        __syncthreads();

        const ulonglong2* wr = (const ulonglong2*)(W3s + tid * 132);
        // bfe3 pass 1
        {
            ull acc[4] = {0ull, 0ull, 0ull, 0ull};
#pragma unroll
            for (int kc = 0; kc < 8; kc++) {
                ulonglong2 wa = wr[kc*4], wb = wr[kc*4+1], wc = wr[kc*4+2], wd = wr[kc*4+3];
#pragma unroll
                for (int b = 0; b < 4; b++) {
                    const ulonglong2* xr = (const ulonglong2*)(x17s + b * 128 + kc * 16);
                    ulonglong2 xa = xr[0], xb = xr[1], xc = xr[2], xd = xr[3];
                    acc[b] = ffma2(xa.x, wa.x, acc[b]); acc[b] = ffma2(xa.y, wa.y, acc[b]);
                    acc[b] = ffma2(xb.x, wb.x, acc[b]); acc[b] = ffma2(xb.y, wb.y, acc[b]);
                    acc[b] = ffma2(xc.x, wc.x, acc[b]); acc[b] = ffma2(xc.y, wc.y, acc[b]);
                    acc[b] = ffma2(xd.x, wd.x, acc[b]); acc[b] = ffma2(xd.y, wd.y, acc[b]);
                }
            }
#pragma unroll
            for (int b = 0; b < 4; b++)
                x18s[b * 128 + tid] = mish(fmaf(hsum(acc[b]), s3, o3));
        }
        __syncthreads();

        // bfe3 pass 2 + scattered store
        {
            ull acc[4] = {0ull, 0ull, 0ull, 0ull};
#pragma unroll
            for (int kc = 0; kc < 8; kc++) {
                ulonglong2 wa = wr[kc*4], wb = wr[kc*4+1], wc = wr[kc*4+2], wd = wr[kc*4+3];
#pragma unroll
                for (int b = 0; b < 4; b++) {
                    const ulonglong2* xr = (const ulonglong2*)(x18s + b * 128 + kc * 16);
                    ulonglong2 xa = xr[0], xb = xr[1], xc = xr[2], xd = xr[3];
                    acc[b] = ffma2(xa.x, wa.x, acc[b]); acc[b] = ffma2(xa.y, wa.y, acc[b]);
                    acc[b] = ffma2(xb.x, wb.x, acc[b]); acc[b] = ffma2(xb.y, wb.y, acc[b]);
                    acc[b] = ffma2(xc.x, wc.x, acc[b]); acc[b] = ffma2(xc.y, wc.y, acc[b]);
                    acc[b] = ffma2(xd.x, wd.x, acc[b]); acc[b] = ffma2(xd.y, wd.y, acc[b]);
                }
            }
#pragma unroll
            for (int b = 0; b < 4; b++) {
                int cell = cellS[b];
                if (cell >= 0) {
                    float x19 = mish(fmaf(hsum(acc[b]), s3, o3));
                    int cy = cell / BEVW;
                    int cx = cell - cy * BEVW;
                    out[tid * NCELL + cx * BEVH + cy] = x19;
                }
            }
        }
        __syncthreads();
    }
}

// ---------------- launcher ----------------
extern "C" void kernel_launch(void* const* d_in, const int* in_sizes, int n_in,
                              void* d_out, int out_size) {
    const float* feat   = (const float*)d_in[0];
    const int*   coors  = (const int*)d_in[1];
    const int*   nvox   = (const int*)d_in[2];
    const float* vfe1_W = (const float*)d_in[3];
    const float* vfe1_b = (const float*)d_in[4];
    const float* vfe2_W = (const float*)d_in[5];
    const float* vfe2_b = (const float*)d_in[6];
    const float* vfe3_W = (const float*)d_in[7];
    const float* vfe3_b = (const float*)d_in[8];
    const float* vfe4_W = (const float*)d_in[9];
    const float* vfe4_b = (const float*)d_in[10];
    const float* bfe1_W = (const float*)d_in[11];
    const float* bfe1_b = (const float*)d_in[12];
    const float* bfe2_W = (const float*)d_in[13];
    const float* bfe2_b = (const float*)d_in[14];
    const float* bfe3_W = (const float*)d_in[15];
    const float* bfe3_b = (const float*)d_in[16];
    float* out = (float*)d_out;

    cudaFuncSetAttribute(k_vfe, cudaFuncAttributeMaxDynamicSharedMemorySize, VFE_SMEM);
    cudaFuncSetAttribute(k_bfe, cudaFuncAttributeMaxDynamicSharedMemorySize, BFE_SMEM);

    // Order chosen so launch index 3 (the one ncu captures) is k_vfe.
    k_zero_meta<<<(NCELL + 255) / 256, 256>>>();
    k_count<<<(NVOX + 255) / 256, 256>>>(coors);
    k_build<<<(NCELL + 255) / 256, 256>>>();
    k_vfe<<<296, 256, VFE_SMEM>>>(feat, nvox, vfe1_W, vfe1_b, vfe2_W, vfe2_b,
                                  vfe3_W, vfe3_b, vfe4_W, vfe4_b);
    k_zero_out<<<4096, 256>>>((float4*)d_out, out_size / 4);
    k_bfe<<<296, 128, BFE_SMEM>>>(out, bfe1_W, bfe1_b, bfe2_W, bfe2_b,
                                  bfe3_W, bfe3_b);
}